// round 7
// baseline (speedup 1.0000x reference)
#include <cuda_runtime.h>
#include <cstdint>

#define NB      16384
#define DTC     0.1f
#define FPB     128
#define THREADS 384

// ---------------- smem layout (words) ----------------
#define PS   264
#define RS   (4 * PS)              // 1056
#define SBUF (16 * RS)             // 16896 (single staging buffer)
#define MEAS_OFF SBUF
#define MEAS_BUF 2048              // [m2][q2][f128][4]
#define CTRL_OFF (MEAS_OFF + 2 * MEAS_BUF)
#define CTRL_BUF 2048              // [q4][f128][4]
#define SMEM_WORDS (CTRL_OFF + 2 * CTRL_BUF)
#define SMEM_BYTES (SMEM_WORDS * 4)   // 100352 B

__constant__ int ROWMAP[22] = {0,1,2,3,4,5,
                               6,7,8,9, 7,10,11,12, 8,11,13,14, 9,12,14,15};

struct St  { float x0,x1,x2,x3,p00,p01,p02,p03,p11,p12,p13,p22,p23,p33; };
struct Cst { float q00,q01,q02,q03,q11,q12,q13,q22,q23,q33,r00,r01,r11; };

__device__ __forceinline__ void cp16(uint32_t dst, const float* src) {
    asm volatile("cp.async.ca.shared.global [%0], [%1], 16;\n" :: "r"(dst), "l"(src));
}

// 128-thread cooperative, sector-packed prefetch of one 8-step chunk
__device__ __forceinline__ void issue_full(
    uint32_t su, const float* __restrict__ meas, const float* __restrict__ ctrl,
    int b0, int ltid, int buf, int s0)
{
#pragma unroll
    for (int j = 0; j < 4; j++) {                 // meas: 2m x 2q x 128f
        int id = ltid + 128 * j;
        int f = id & 127, q = (id >> 7) & 1, m = id >> 8;
        cp16(su + (uint32_t)(MEAS_OFF + buf * MEAS_BUF + ((m * 2 + q) * 128 + f) * 4) * 4,
             meas + (size_t)(b0 + f) * 200 + m * 100 + s0 + 4 * q);
    }
#pragma unroll
    for (int j = 0; j < 4; j++) {                 // ctrl: 4q x 128f
        int id = ltid + 128 * j;
        int f = id & 127, q = id >> 7;
        cp16(su + (uint32_t)(CTRL_OFF + buf * CTRL_BUF + (q * 128 + f) * 4) * 4,
             ctrl + (size_t)(b0 + f) * 200 + 2 * s0 + 4 * q);
    }
    asm volatile("cp.async.commit_group;\n" ::: "memory");
}

// tail chunk (4 steps at s0 = 96)
__device__ __forceinline__ void issue_tail(
    uint32_t su, const float* __restrict__ meas, const float* __restrict__ ctrl,
    int b0, int ltid, int buf)
{
#pragma unroll
    for (int j = 0; j < 2; j++) {
        int id = ltid + 128 * j;
        int f = id & 127, m = id >> 7;
        cp16(su + (uint32_t)(MEAS_OFF + buf * MEAS_BUF + ((m * 2) * 128 + f) * 4) * 4,
             meas + (size_t)(b0 + f) * 200 + m * 100 + 96);
    }
#pragma unroll
    for (int j = 0; j < 2; j++) {
        int id = ltid + 128 * j;
        int f = id & 127, q = id >> 7;
        cp16(su + (uint32_t)(CTRL_OFF + buf * CTRL_BUF + (q * 128 + f) * 4) * 4,
             ctrl + (size_t)(b0 + f) * 200 + 192 + 4 * q);
    }
    asm volatile("cp.async.commit_group;\n" ::: "memory");
}

// one exact-collapsed UKF step; Pn via K*A_c^T (== K S K^T since K = A_c S^-1)
template <bool STAGE>
__device__ __forceinline__ void ukf_step(
    St& s, const Cst& c, float z0, float z1, float ux, float uy, float* o)
{
    const float xp0 = s.x0 + DTC * s.x2 + 0.5f * DTC * DTC * ux;
    const float xp1 = s.x1 + DTC * s.x3 + 0.5f * DTC * DTC * uy;
    const float xp2 = s.x2 + DTC * ux;
    const float xp3 = s.x3 + DTC * uy;

    const float a02 = s.p02 + DTC * s.p22;
    const float a03 = s.p03 + DTC * s.p23;
    const float a12 = s.p12 + DTC * s.p23;
    const float a13 = s.p13 + DTC * s.p33;
    const float a00 = s.p00 + DTC * s.p02 + DTC * a02;
    const float a11 = s.p11 + DTC * s.p13 + DTC * a13;
    const float a01 = s.p01 + DTC * s.p03 + DTC * a12;

    const float s00 = a00 + c.r00;
    const float s01 = a01 + c.r01;
    const float s11 = a11 + c.r11;
    const float idet = __fdividef(1.0f, s00 * s11 - s01 * s01);
    const float i00 =  s11 * idet;
    const float i01 = -s01 * idet;
    const float i11 =  s00 * idet;

    const float K00 = a00 * i00 + a01 * i01, K01 = a00 * i01 + a01 * i11;
    const float K10 = a01 * i00 + a11 * i01, K11 = a01 * i01 + a11 * i11;
    const float K20 = a02 * i00 + a12 * i01, K21 = a02 * i01 + a12 * i11;
    const float K30 = a03 * i00 + a13 * i01, K31 = a03 * i01 + a13 * i11;

    const float in0 = z0 - xp0, in1 = z1 - xp1;
    const float xn0 = xp0 + K00 * in0 + K01 * in1;
    const float xn1 = xp1 + K10 * in0 + K11 * in1;
    const float xn2 = xp2 + K20 * in0 + K21 * in1;
    const float xn3 = xp3 + K30 * in0 + K31 * in1;

    s.p00 = (a00 + c.q00) - (K00 * a00 + K01 * a01);
    s.p01 = (a01 + c.q01) - (K00 * a01 + K01 * a11);
    s.p02 = (a02 + c.q02) - (K00 * a02 + K01 * a12);
    s.p03 = (a03 + c.q03) - (K00 * a03 + K01 * a13);
    s.p11 = (a11 + c.q11) - (K10 * a01 + K11 * a11);
    s.p12 = (a12 + c.q12) - (K10 * a02 + K11 * a12);
    s.p13 = (a13 + c.q13) - (K10 * a03 + K11 * a13);
    s.p22 = (s.p22 + c.q22) - (K20 * a02 + K21 * a12);
    s.p23 = (s.p23 + c.q23) - (K20 * a03 + K21 * a13);
    s.p33 = (s.p33 + c.q33) - (K30 * a03 + K31 * a13);
    s.x0 = xn0; s.x1 = xn1; s.x2 = xn2; s.x3 = xn3;

    if (STAGE) {
        o[0] = xp0;  o[1] = xp1;
        o[2] = xn0;  o[3] = xn1;  o[4] = xn2;  o[5] = xn3;
        o[6]  = s.p00; o[7]  = s.p01; o[8]  = s.p02; o[9]  = s.p03;
        o[10] = s.p11; o[11] = s.p12; o[12] = s.p13;
        o[13] = s.p22; o[14] = s.p23; o[15] = s.p33;
    }
}

// NS steps from input buffer ibuf; STAGE => write pairs into `stage`
template <int NS, bool STAGE>
__device__ __forceinline__ void compute_chunk(
    St& s, const Cst& c, const float* sm, float* stage, int ibuf, int ftid)
{
    const float* mb = sm + MEAS_OFF + ibuf * MEAS_BUF;
    const float* cb = sm + CTRL_OFF + ibuf * CTRL_BUF;

    float4 z0q[2], z1q[2], cq[4];
    z0q[0] = *reinterpret_cast<const float4*>(mb + (0 * 128 + ftid) * 4);
    z1q[0] = *reinterpret_cast<const float4*>(mb + (2 * 128 + ftid) * 4);
    cq[0]  = *reinterpret_cast<const float4*>(cb + (0 * 128 + ftid) * 4);
    cq[1]  = *reinterpret_cast<const float4*>(cb + (1 * 128 + ftid) * 4);
    if (NS == 8) {
        z0q[1] = *reinterpret_cast<const float4*>(mb + (1 * 128 + ftid) * 4);
        z1q[1] = *reinterpret_cast<const float4*>(mb + (3 * 128 + ftid) * 4);
        cq[2]  = *reinterpret_cast<const float4*>(cb + (2 * 128 + ftid) * 4);
        cq[3]  = *reinterpret_cast<const float4*>(cb + (3 * 128 + ftid) * 4);
    } else {
        z0q[1] = z0q[0]; z1q[1] = z1q[0]; cq[2] = cq[0]; cq[3] = cq[1];
    }
    const float z0s[8] = {z0q[0].x,z0q[0].y,z0q[0].z,z0q[0].w,
                          z0q[1].x,z0q[1].y,z0q[1].z,z0q[1].w};
    const float z1s[8] = {z1q[0].x,z1q[0].y,z1q[0].z,z1q[0].w,
                          z1q[1].x,z1q[1].y,z1q[1].z,z1q[1].w};
    const float uxs[8] = {cq[0].x,cq[0].z,cq[1].x,cq[1].z,
                          cq[2].x,cq[2].z,cq[3].x,cq[3].z};
    const float uys[8] = {cq[0].y,cq[0].w,cq[1].y,cq[1].w,
                          cq[2].y,cq[2].w,cq[3].y,cq[3].w};

    float prev[16];
#pragma unroll
    for (int sp = 0; sp < NS; sp++) {
        float cur[16];
        ukf_step<STAGE>(s, c, z0s[sp], z1s[sp], uxs[sp], uys[sp], cur);
        if (STAGE) {
            if (sp & 1) {
                float* sb = stage + (sp >> 1) * PS + ftid * 2;
#pragma unroll
                for (int r = 0; r < 16; r++)
                    *reinterpret_cast<float2*>(sb + r * RS) =
                        make_float2(prev[r], cur[r]);
            } else {
#pragma unroll
                for (int r = 0; r < 16; r++) prev[r] = cur[r];
            }
        }
    }
}

// flush one 8-step chunk: 5632 items = 22R x 128f x 2h, all 384 threads
__device__ __forceinline__ void flush_full(
    const float* __restrict__ stage, float* __restrict__ preds,
    float* __restrict__ states, float* __restrict__ covs, int blk, int tid, int s0)
{
#pragma unroll
    for (int k = 0; k < 15; k++) {
        const int id = tid + THREADS * k;
        if (id < 5632) {
            const int h = id & 1, f = (id >> 1) & 127, R = id >> 8;
            const int r = ROWMAP[R];
            const int gb = blk * FPB + f;
            const float* base = stage + r * RS + (2 * h) * PS + f * 2;
            float2 lo = *reinterpret_cast<const float2*>(base);
            float2 hi = *reinterpret_cast<const float2*>(base + PS);
            float4 v = make_float4(lo.x, lo.y, hi.x, hi.y);
            float* dst = (R < 2) ? preds  + (size_t)gb * 200  + R * 100
                       : (R < 6) ? states + (size_t)gb * 400  + (R - 2) * 100
                                 : covs   + (size_t)gb * 1600 + (R - 6) * 100;
            *reinterpret_cast<float4*>(dst + s0 + 4 * h) = v;
        }
    }
}

// tail flush: 2816 items = 22R x 128f, steps 96..99
__device__ __forceinline__ void flush_tail(
    const float* __restrict__ stage, float* __restrict__ preds,
    float* __restrict__ states, float* __restrict__ covs, int blk, int tid)
{
#pragma unroll
    for (int k = 0; k < 8; k++) {
        const int id = tid + THREADS * k;
        if (id < 2816) {
            const int f = id & 127, R = id >> 7;
            const int r = ROWMAP[R];
            const int gb = blk * FPB + f;
            const float* base = stage + r * RS + f * 2;
            float2 lo = *reinterpret_cast<const float2*>(base);
            float2 hi = *reinterpret_cast<const float2*>(base + PS);
            float4 v = make_float4(lo.x, lo.y, hi.x, hi.y);
            float* dst = (R < 2) ? preds  + (size_t)gb * 200  + R * 100
                       : (R < 6) ? states + (size_t)gb * 400  + (R - 2) * 100
                                 : covs   + (size_t)gb * 1600 + (R - 6) * 100;
            *reinterpret_cast<float4*>(dst + 96) = v;
        }
    }
}

__global__ __launch_bounds__(THREADS, 1) void ukf_kernel(
    const float* __restrict__ meas, const float* __restrict__ state0,
    const float* __restrict__ cov0, const float* __restrict__ ctrl,
    const float* __restrict__ Qm,   const float* __restrict__ Rm,
    float* __restrict__ preds, float* __restrict__ states, float* __restrict__ covs)
{
    extern __shared__ float sm[];
    const uint32_t su = (uint32_t)__cvta_generic_to_shared(sm);
    const int tid  = threadIdx.x;
    const int role = tid >> 7;          // 0,1,2 -> one warp of each role per SMSP
    const int ftid = tid & 127;
    const int blk  = blockIdx.x;
    const int b0   = blk * FPB;
    const int b    = b0 + ftid;

    St s;
    {
        float4 xv = *reinterpret_cast<const float4*>(state0 + (size_t)b * 4);
        s.x0 = xv.x; s.x1 = xv.y; s.x2 = xv.z; s.x3 = xv.w;
        const float4* pv = reinterpret_cast<const float4*>(cov0 + (size_t)b * 16);
        float4 r0 = pv[0], r1 = pv[1], r2 = pv[2], r3 = pv[3];
        s.p00 = r0.x; s.p01 = r0.y; s.p02 = r0.z; s.p03 = r0.w;
        s.p11 = r1.y; s.p12 = r1.z; s.p13 = r1.w;
        s.p22 = r2.z; s.p23 = r2.w; s.p33 = r3.w;
    }
    Cst c;
    c.q00 = Qm[0];  c.q01 = Qm[1];  c.q02 = Qm[2];  c.q03 = Qm[3];
    c.q11 = Qm[5];  c.q12 = Qm[6];  c.q13 = Qm[7];
    c.q22 = Qm[10]; c.q23 = Qm[11]; c.q33 = Qm[15];
    c.r00 = Rm[0];  c.r01 = Rm[1];  c.r11 = Rm[3];

    float* stage = sm;

    if (role == 2) issue_full(su, meas, ctrl, b0, ftid, 0, 0);

#pragma unroll 1
    for (int ch = 0; ch < 13; ch++) {
        if (role == 2) {
            if (ch < 11)       issue_full(su, meas, ctrl, b0, ftid, (ch + 1) & 1, (ch + 1) * 8);
            else if (ch == 11) issue_tail(su, meas, ctrl, b0, ftid, 0);
            if (ch < 12) asm volatile("cp.async.wait_group 1;\n" ::: "memory");
            else         asm volatile("cp.async.wait_group 0;\n" ::: "memory");
        }
        __syncthreads();                      // inputs(ch) visible; stage reusable
        const int ibuf = ch & 1;

        if (ch < 9) {
            // role0 stages steps 0..71; roles 1,2 recompute light
            if (role == 0) compute_chunk<8, true >(s, c, sm, stage, ibuf, ftid);
            else           compute_chunk<8, false>(s, c, sm, stage, ibuf, ftid);
        } else if (ch < 12) {
            // role1 stages steps 72..95; role2 light; role0 idle
            if      (role == 1) compute_chunk<8, true >(s, c, sm, stage, ibuf, ftid);
            else if (role == 2) compute_chunk<8, false>(s, c, sm, stage, ibuf, ftid);
        } else {
            // role2 stages steps 96..99
            if (role == 2) compute_chunk<4, true>(s, c, sm, stage, ibuf, ftid);
        }

        __syncthreads();                      // staging complete
        if (ch < 12) flush_full(stage, preds, states, covs, blk, tid, ch * 8);
        else         flush_tail(stage, preds, states, covs, blk, tid);
    }
}

extern "C" void kernel_launch(void* const* d_in, const int* in_sizes, int n_in,
                              void* d_out, int out_size)
{
    const float* meas  = (const float*)d_in[0];
    const float* state = (const float*)d_in[1];
    const float* cov   = (const float*)d_in[2];
    const float* ctrl  = (const float*)d_in[3];
    const float* Q     = (const float*)d_in[4];
    const float* R     = (const float*)d_in[5];

    float* out    = (float*)d_out;
    float* preds  = out;                         // 16384*2*100
    float* states = preds  + (size_t)NB * 200;   // 16384*4*100
    float* covs   = states + (size_t)NB * 400;   // 16384*16*100

    static int smem_set = 0;
    if (!smem_set) {
        cudaFuncSetAttribute(ukf_kernel,
                             cudaFuncAttributeMaxDynamicSharedMemorySize, SMEM_BYTES);
        smem_set = 1;
    }

    ukf_kernel<<<NB / FPB, THREADS, SMEM_BYTES>>>(meas, state, cov, ctrl, Q, R,
                                                  preds, states, covs);
}

// round 8
// speedup vs baseline: 1.3000x; 1.3000x over previous
#include <cuda_runtime.h>
#include <cstdint>

#define NB    16384
#define DTC   0.1f
#define FPB   16
#define THREADS 128

// ---------------- smem layout (words) ----------------
// staging: [f16][r16][s100] with per-filter stride 1602 (pad 2: conflict-free STS)
#define FSTRIDE 1602
#define STAGE_WORDS (16 * FSTRIDE)          // 25632
#define MEAS_OFF  STAGE_WORDS               // [buf][m2][q2][f16][4]
#define MEAS_BUF  256
#define CTRL_OFF  (MEAS_OFF + 2 * MEAS_BUF) // [buf][q4][f16][4]
#define CTRL_BUF  256
#define SMEM_WORDS (CTRL_OFF + 2 * CTRL_BUF)
#define SMEM_BYTES (SMEM_WORDS * 4)         // 106624 B -> 2 blocks/SM

__constant__ int CMAP[16] = {6,7,8,9, 7,10,11,12, 8,11,13,14, 9,12,14,15};

struct St  { float x0,x1,x2,x3,p00,p01,p02,p03,p11,p12,p13,p22,p23,p33; };
struct Cst { float q00,q01,q02,q03,q11,q12,q13,q22,q23,q33,r00,r01,r11; };

__device__ __forceinline__ void cp16(uint32_t dst, const float* src) {
    asm volatile("cp.async.ca.shared.global [%0], [%1], 16;\n" :: "r"(dst), "l"(src));
}

// one 8-step chunk of inputs: 128 cp16 ops, one per thread
__device__ __forceinline__ void issue_full(
    uint32_t su, const float* __restrict__ meas, const float* __restrict__ ctrl,
    int b0, int tid, int buf, int s0)
{
    if (tid < 64) {           // meas: 2m x 2q x 16f
        int f = tid & 15, q = (tid >> 4) & 1, m = tid >> 5;
        cp16(su + (uint32_t)(MEAS_OFF + buf * MEAS_BUF + ((m * 2 + q) * 16 + f) * 4) * 4,
             meas + (size_t)(b0 + f) * 200 + m * 100 + s0 + 4 * q);
    } else {                  // ctrl: 4q x 16f
        int id = tid - 64;
        int f = id & 15, q = id >> 4;
        cp16(su + (uint32_t)(CTRL_OFF + buf * CTRL_BUF + (q * 16 + f) * 4) * 4,
             ctrl + (size_t)(b0 + f) * 200 + 2 * s0 + 4 * q);
    }
    asm volatile("cp.async.commit_group;\n" ::: "memory");
}

// tail (4 steps at s0=96): 64 ops
__device__ __forceinline__ void issue_tail(
    uint32_t su, const float* __restrict__ meas, const float* __restrict__ ctrl,
    int b0, int tid, int buf)
{
    if (tid < 32) {           // meas: 2m x 16f, q=0
        int f = tid & 15, m = tid >> 4;
        cp16(su + (uint32_t)(MEAS_OFF + buf * MEAS_BUF + ((m * 2) * 16 + f) * 4) * 4,
             meas + (size_t)(b0 + f) * 200 + m * 100 + 96);
    } else if (tid < 64) {    // ctrl: 2q x 16f
        int id = tid - 32;
        int f = id & 15, q = id >> 4;
        cp16(su + (uint32_t)(CTRL_OFF + buf * CTRL_BUF + (q * 16 + f) * 4) * 4,
             ctrl + (size_t)(b0 + f) * 200 + 192 + 4 * q);
    }
    asm volatile("cp.async.commit_group;\n" ::: "memory");
}

// one exact-collapsed UKF step; Pn via K*A_c^T (== K S K^T since K = A_c S^-1)
__device__ __forceinline__ void ukf_step(
    St& s, const Cst& c, float z0, float z1, float ux, float uy,
    float* stage_f, int sp)
{
    const float xp0 = s.x0 + DTC * s.x2 + 0.5f * DTC * DTC * ux;
    const float xp1 = s.x1 + DTC * s.x3 + 0.5f * DTC * DTC * uy;
    const float xp2 = s.x2 + DTC * ux;
    const float xp3 = s.x3 + DTC * uy;

    const float a02 = s.p02 + DTC * s.p22;
    const float a03 = s.p03 + DTC * s.p23;
    const float a12 = s.p12 + DTC * s.p23;
    const float a13 = s.p13 + DTC * s.p33;
    const float a00 = s.p00 + DTC * s.p02 + DTC * a02;
    const float a11 = s.p11 + DTC * s.p13 + DTC * a13;
    const float a01 = s.p01 + DTC * s.p03 + DTC * a12;

    const float s00 = a00 + c.r00;
    const float s01 = a01 + c.r01;
    const float s11 = a11 + c.r11;
    const float idet = __fdividef(1.0f, s00 * s11 - s01 * s01);
    const float i00 =  s11 * idet;
    const float i01 = -s01 * idet;
    const float i11 =  s00 * idet;

    const float K00 = a00 * i00 + a01 * i01, K01 = a00 * i01 + a01 * i11;
    const float K10 = a01 * i00 + a11 * i01, K11 = a01 * i01 + a11 * i11;
    const float K20 = a02 * i00 + a12 * i01, K21 = a02 * i01 + a12 * i11;
    const float K30 = a03 * i00 + a13 * i01, K31 = a03 * i01 + a13 * i11;

    const float in0 = z0 - xp0, in1 = z1 - xp1;
    const float xn0 = xp0 + K00 * in0 + K01 * in1;
    const float xn1 = xp1 + K10 * in0 + K11 * in1;
    const float xn2 = xp2 + K20 * in0 + K21 * in1;
    const float xn3 = xp3 + K30 * in0 + K31 * in1;

    s.p00 = (a00 + c.q00) - (K00 * a00 + K01 * a01);
    s.p01 = (a01 + c.q01) - (K00 * a01 + K01 * a11);
    s.p02 = (a02 + c.q02) - (K00 * a02 + K01 * a12);
    s.p03 = (a03 + c.q03) - (K00 * a03 + K01 * a13);
    s.p11 = (a11 + c.q11) - (K10 * a01 + K11 * a11);
    s.p12 = (a12 + c.q12) - (K10 * a02 + K11 * a12);
    s.p13 = (a13 + c.q13) - (K10 * a03 + K11 * a13);
    s.p22 = (s.p22 + c.q22) - (K20 * a02 + K21 * a12);
    s.p23 = (s.p23 + c.q23) - (K20 * a03 + K21 * a13);
    s.p33 = (s.p33 + c.q33) - (K30 * a03 + K31 * a13);
    s.x0 = xn0; s.x1 = xn1; s.x2 = xn2; s.x3 = xn3;

    // stage the 16 unique rows at [r][sp]
    stage_f[ 0 * 100 + sp] = xp0;   stage_f[ 1 * 100 + sp] = xp1;
    stage_f[ 2 * 100 + sp] = xn0;   stage_f[ 3 * 100 + sp] = xn1;
    stage_f[ 4 * 100 + sp] = xn2;   stage_f[ 5 * 100 + sp] = xn3;
    stage_f[ 6 * 100 + sp] = s.p00; stage_f[ 7 * 100 + sp] = s.p01;
    stage_f[ 8 * 100 + sp] = s.p02; stage_f[ 9 * 100 + sp] = s.p03;
    stage_f[10 * 100 + sp] = s.p11; stage_f[11 * 100 + sp] = s.p12;
    stage_f[12 * 100 + sp] = s.p13; stage_f[13 * 100 + sp] = s.p22;
    stage_f[14 * 100 + sp] = s.p23; stage_f[15 * 100 + sp] = s.p33;
}

__global__ __launch_bounds__(THREADS) void ukf_kernel(
    const float* __restrict__ meas, const float* __restrict__ state0,
    const float* __restrict__ cov0, const float* __restrict__ ctrl,
    const float* __restrict__ Qm,   const float* __restrict__ Rm,
    float* __restrict__ preds, float* __restrict__ states, float* __restrict__ covs)
{
    extern __shared__ float sm[];
    const uint32_t su = (uint32_t)__cvta_generic_to_shared(sm);
    const int tid = threadIdx.x;
    const int blk = blockIdx.x;
    const int b0  = blk * FPB;

    // constants (all threads; cheap)
    Cst c;
    c.q00 = Qm[0];  c.q01 = Qm[1];  c.q02 = Qm[2];  c.q03 = Qm[3];
    c.q11 = Qm[5];  c.q12 = Qm[6];  c.q13 = Qm[7];
    c.q22 = Qm[10]; c.q23 = Qm[11]; c.q33 = Qm[15];
    c.r00 = Rm[0];  c.r01 = Rm[1];  c.r11 = Rm[3];

    // per-filter state for compute lanes (tid < 16)
    St s;
    if (tid < 16) {
        const int b = b0 + tid;
        float4 xv = *reinterpret_cast<const float4*>(state0 + (size_t)b * 4);
        s.x0 = xv.x; s.x1 = xv.y; s.x2 = xv.z; s.x3 = xv.w;
        const float4* pv = reinterpret_cast<const float4*>(cov0 + (size_t)b * 16);
        float4 r0 = pv[0], r1 = pv[1], r2 = pv[2], r3 = pv[3];
        s.p00 = r0.x; s.p01 = r0.y; s.p02 = r0.z; s.p03 = r0.w;
        s.p11 = r1.y; s.p12 = r1.z; s.p13 = r1.w;
        s.p22 = r2.z; s.p23 = r2.w; s.p33 = r3.w;
    }

    float* stage_f = sm + (tid & 15) * FSTRIDE;

    issue_full(su, meas, ctrl, b0, tid, 0, 0);

#pragma unroll 1
    for (int ch = 0; ch < 13; ch++) {
        if (ch < 11)       issue_full(su, meas, ctrl, b0, tid, (ch + 1) & 1, (ch + 1) * 8);
        else if (ch == 11) issue_tail(su, meas, ctrl, b0, tid, 0);
        if (ch < 12) asm volatile("cp.async.wait_group 1;\n" ::: "memory");
        else         asm volatile("cp.async.wait_group 0;\n" ::: "memory");
        __syncthreads();                       // inputs(ch) visible

        if (tid < 16) {
            const float* mb = sm + MEAS_OFF + (ch & 1) * MEAS_BUF;
            const float* cb = sm + CTRL_OFF + (ch & 1) * CTRL_BUF;
            const int nsteps = (ch < 12) ? 8 : 4;
            // load chunk inputs (float4, conflict-light)
            float4 z0q0 = *reinterpret_cast<const float4*>(mb + (0 * 16 + tid) * 4);
            float4 z0q1 = *reinterpret_cast<const float4*>(mb + (1 * 16 + tid) * 4);
            float4 z1q0 = *reinterpret_cast<const float4*>(mb + (2 * 16 + tid) * 4);
            float4 z1q1 = *reinterpret_cast<const float4*>(mb + (3 * 16 + tid) * 4);
            float4 cq0  = *reinterpret_cast<const float4*>(cb + (0 * 16 + tid) * 4);
            float4 cq1  = *reinterpret_cast<const float4*>(cb + (1 * 16 + tid) * 4);
            float4 cq2  = *reinterpret_cast<const float4*>(cb + (2 * 16 + tid) * 4);
            float4 cq3  = *reinterpret_cast<const float4*>(cb + (3 * 16 + tid) * 4);
            const float z0s[8] = {z0q0.x,z0q0.y,z0q0.z,z0q0.w, z0q1.x,z0q1.y,z0q1.z,z0q1.w};
            const float z1s[8] = {z1q0.x,z1q0.y,z1q0.z,z1q0.w, z1q1.x,z1q1.y,z1q1.z,z1q1.w};
            const float uxs[8] = {cq0.x,cq0.z,cq1.x,cq1.z, cq2.x,cq2.z,cq3.x,cq3.z};
            const float uys[8] = {cq0.y,cq0.w,cq1.y,cq1.w, cq2.y,cq2.w,cq3.y,cq3.w};
            const int sbase = ch * 8;
#pragma unroll
            for (int sp = 0; sp < 8; sp++) {
                if (sp < nsteps)
                    ukf_step(s, c, z0s[sp], z1s[sp], uxs[sp], uys[sp],
                             stage_f, sbase + sp);
            }
        }
        __syncthreads();                       // input buffer reusable
    }

    // ---------------- single dense flush ----------------
    // preds: 16f x 2r x 25 float4  (800 items) — contiguous per filter block
#pragma unroll 1
    for (int k = 0; k < 7; k++) {
        const int id = tid + 128 * k;
        if (id < 800) {
            const int f = id / 50, rem = id % 50;      // rem = R*25 + g
            const int r = rem / 25, g = rem % 25;
            const float* sp_ = sm + f * FSTRIDE + r * 100 + g * 4;
            float4 v = make_float4(sp_[0], sp_[1], sp_[2], sp_[3]);
            *reinterpret_cast<float4*>(preds + (size_t)(b0 + f) * 200 + rem * 4) = v;
        }
    }
    // states: 16f x 4r x 25 (1600 items), staged rows 2..5
#pragma unroll 1
    for (int k = 0; k < 13; k++) {
        const int id = tid + 128 * k;
        if (id < 1600) {
            const int f = id / 100, rem = id % 100;
            const int r = 2 + rem / 25, g = rem % 25;
            const float* sp_ = sm + f * FSTRIDE + r * 100 + g * 4;
            float4 v = make_float4(sp_[0], sp_[1], sp_[2], sp_[3]);
            *reinterpret_cast<float4*>(states + (size_t)(b0 + f) * 400 + rem * 4) = v;
        }
    }
    // covs: 16f x 16R x 25 (6400 items), rows via CMAP (mirror duplicates)
#pragma unroll 1
    for (int k = 0; k < 50; k++) {
        const int id = tid + 128 * k;
        const int f = id / 400, rem = id % 400;
        const int r = CMAP[rem / 25], g = rem % 25;
        const float* sp_ = sm + f * FSTRIDE + r * 100 + g * 4;
        float4 v = make_float4(sp_[0], sp_[1], sp_[2], sp_[3]);
        *reinterpret_cast<float4*>(covs + (size_t)(b0 + f) * 1600 + rem * 4) = v;
    }
}

extern "C" void kernel_launch(void* const* d_in, const int* in_sizes, int n_in,
                              void* d_out, int out_size)
{
    const float* meas  = (const float*)d_in[0];
    const float* state = (const float*)d_in[1];
    const float* cov   = (const float*)d_in[2];
    const float* ctrl  = (const float*)d_in[3];
    const float* Q     = (const float*)d_in[4];
    const float* R     = (const float*)d_in[5];

    float* out    = (float*)d_out;
    float* preds  = out;                         // 16384*2*100
    float* states = preds  + (size_t)NB * 200;   // 16384*4*100
    float* covs   = states + (size_t)NB * 400;   // 16384*16*100

    static int smem_set = 0;
    if (!smem_set) {
        cudaFuncSetAttribute(ukf_kernel,
                             cudaFuncAttributeMaxDynamicSharedMemorySize, SMEM_BYTES);
        smem_set = 1;
    }

    ukf_kernel<<<NB / FPB, THREADS, SMEM_BYTES>>>(meas, state, cov, ctrl, Q, R,
                                                  preds, states, covs);
}